// round 14
// baseline (speedup 1.0000x reference)
#include <cuda_runtime.h>
#include <math.h>
#include <stdint.h>

#define SEQ 1024
#define BB  64
#define DD  512
#define HH  512
#define BH  (BB * HH)

#define NTHR 256
#define ROWS 16      // batch rows per CTA
#define COLS 32      // cols per CTA

typedef unsigned long long u64;

// Scratch (allocation-free rule: __device__ globals)
__device__ float g_z0[SEQ * BB * HH];   // x@Wx0 + bx0 + bh0 (b-major)
__device__ float g_h0[SEQ * BB * HH];   // layer-0 hidden history (b-major)
__device__ int   g_flag0[SEQ * 4];      // per (t, batch-group), target 16
__device__ int   g_flag1[SEQ * 4];

// ---------------------------------------------------------------- helpers
__device__ __forceinline__ int ld_acq(const int* p) {
    int v;
    asm volatile("ld.acquire.gpu.s32 %0, [%1];" : "=r"(v) : "l"(p) : "memory");
    return v;
}
__device__ __forceinline__ void red_release(int* p) {
    asm volatile("red.release.gpu.global.add.s32 [%0], 1;" :: "l"(p) : "memory");
}
__device__ __forceinline__ void wait_flag(const int* p, int target) {
    while (ld_acq(p) < target) {}
}
__device__ __forceinline__ u64 dup2(float x) {
    u64 r; asm("mov.b64 %0, {%1, %1};" : "=l"(r) : "f"(x)); return r;
}
__device__ __forceinline__ void fma2(u64& acc, u64 a, u64 b) {
    asm("fma.rn.f32x2 %0, %1, %2, %0;" : "+l"(acc) : "l"(a), "l"(b));
}
__device__ __forceinline__ float2 unp2(u64 v) {
    float2 f; asm("mov.b64 {%0, %1}, %2;" : "=f"(f.x), "=f"(f.y) : "l"(v)); return f;
}
__device__ __forceinline__ float fold2(u64 v) {
    float2 f = unp2(v); return f.x + f.y;
}
__device__ __forceinline__ void cp16(uint32_t s, const void* g) {
    asm volatile("cp.async.cg.shared.global [%0], [%1], 16;" :: "r"(s), "l"(g));
}
__device__ __forceinline__ void cp_commit() {
    asm volatile("cp.async.commit_group;" ::: "memory");
}
#define CP_WAIT(N) asm volatile("cp.async.wait_group %0;" :: "n"(N) : "memory")

// w layout: 4 cg-groups of [8 rows][WS floats], group stride GS = 8*WS + 8.
// cg lane offsets mod 32 floats = {0,8,16,24} -> distinct quad banks.
#define WS0 512
#define GS0 (8 * WS0 + 8)    // 4104
#define WS1 1024
#define GS1 (8 * WS1 + 8)    // 8200
// h row strides: bp lane offsets mod 32 distinct.
#define HR0 516              // mod 32 = 4  -> {0,4,...,28}
#define HR1 1044             // mod 32 = 20 -> {0,20,8,28,16,4,24,12}
#define RBG 20               // red floats per pos (16 + 4 pad)
#define RSL (32 * RBG)       // 640 floats per k-slice

// Stage 16 rows x 256 k (16KB) into h buffer at column kdst. 4 cp16/thread.
template<int HRW>
__device__ __forceinline__ void stage16k(uint32_t sbase, const float* src,
                                         int kdst, int tid) {
#pragma unroll
    for (int j = 0; j < 4; j++) {
        int id = tid + j * NTHR;            // 0..1023
        int b = id >> 6, ku = id & 63;
        cp16(sbase + (uint32_t)((b * HRW + kdst + ku * 4) * 4),
             src + (size_t)b * HH + ku * 4);
    }
    cp_commit();
}

// NK-k segment: 2 rows x 8 cols per thread, K-packed f32x2.
// h: 8 distinct bp rows x broadcast-4; w: 4 distinct cg quads x broadcast-8.
template<int WS, int NK>
__device__ __forceinline__ void segN(u64* acc, const float* hr0, const float* hr1,
                                     const float* wk)
{
#pragma unroll
    for (int i = 0; i < NK; i += 4) {
        ulonglong2 ha = *(const ulonglong2*)(hr0 + i);
        ulonglong2 hb = *(const ulonglong2*)(hr1 + i);
#pragma unroll
        for (int c = 0; c < 8; c++) {
            ulonglong2 w = *(const ulonglong2*)(wk + c * WS + i);
            fma2(acc[c],     ha.x, w.x);  fma2(acc[c],     ha.y, w.y);
            fma2(acc[8 + c], hb.x, w.x);  fma2(acc[8 + c], hb.y, w.y);
        }
    }
}

// Fold 16 u64 partials to floats, store to red[ks][pos][16] (20-padded).
__device__ __forceinline__ void store_partials(float* redf, const u64* acc,
                                               int ks, int pos) {
    float tmp[16];
#pragma unroll
    for (int j = 0; j < 16; j++) tmp[j] = fold2(acc[j]);
    float* wr = redf + (size_t)ks * RSL + (size_t)pos * RBG;
#pragma unroll
    for (int j = 0; j < 4; j++)
        *(float4*)(wr + 4 * j) = make_float4(tmp[4*j], tmp[4*j+1], tmp[4*j+2], tmp[4*j+3]);
}

// Reduce 8 k-slices for output (local row bl 0..15, col quad cq 0..7).
__device__ __forceinline__ float4 reduce8(const float* redf, int bl, int cq) {
    const float* rp = redf + (size_t)((cq >> 1) * 8 + (bl & 7)) * RBG
                    + (bl >> 3) * 8 + (cq & 1) * 4;
    float4 s = make_float4(0.f, 0.f, 0.f, 0.f);
#pragma unroll
    for (int ks = 0; ks < 8; ks++) {
        float4 p = *(const float4*)(rp + (size_t)ks * RSL);
        s.x += p.x; s.y += p.y; s.z += p.z; s.w += p.w;
    }
    return s;
}

// ---------------------------------------------------------------------------
// Precompute Z0 = X @ Wx0 + bx0 + bh0 + zero the flags.
// ---------------------------------------------------------------------------
__global__ __launch_bounds__(256) void precompute_z0(
    const float* __restrict__ X,
    const float* __restrict__ W,
    const float* __restrict__ bxv,
    const float* __restrict__ bhv)
{
    __shared__ float As[16][64];
    __shared__ float Bs[16][64];
    const int tid = threadIdx.x;

    if (blockIdx.y == 0 && blockIdx.x < 16) {
        int i = blockIdx.x * 256 + tid;     // 0..4095
        g_flag0[i] = 0;
        g_flag1[i] = 0;
    }

    const int tx = tid & 15;
    const int ty = tid >> 4;
    const int m0 = blockIdx.x * 64;
    const int n0 = blockIdx.y * 64;
    const int lm = tid >> 2;
    const int lk = (tid & 3) << 2;
    const int lr = tid >> 4;
    const int lc = (tid & 15) << 2;

    u64 acc[4][2];
#pragma unroll
    for (int i = 0; i < 4; i++) { acc[i][0] = 0ULL; acc[i][1] = 0ULL; }

    for (int kc = 0; kc < DD; kc += 16) {
        float4 a4 = *(const float4*)(X + (size_t)(m0 + lm) * DD + kc + lk);
        float4 b4 = *(const float4*)(W + (size_t)(kc + lr) * HH + n0 + lc);
        As[lk + 0][lm] = a4.x;
        As[lk + 1][lm] = a4.y;
        As[lk + 2][lm] = a4.z;
        As[lk + 3][lm] = a4.w;
        *(float4*)&Bs[lr][lc] = b4;
        __syncthreads();
#pragma unroll
        for (int kk = 0; kk < 16; kk++) {
            float4 av = *(const float4*)&As[kk][ty << 2];
            ulonglong2 bq = *(const ulonglong2*)&Bs[kk][tx << 2];
            u64 d;
            d = dup2(av.x); fma2(acc[0][0], d, bq.x); fma2(acc[0][1], d, bq.y);
            d = dup2(av.y); fma2(acc[1][0], d, bq.x); fma2(acc[1][1], d, bq.y);
            d = dup2(av.z); fma2(acc[2][0], d, bq.x); fma2(acc[2][1], d, bq.y);
            d = dup2(av.w); fma2(acc[3][0], d, bq.x); fma2(acc[3][1], d, bq.y);
        }
        __syncthreads();
    }
    const int n = n0 + (tx << 2);
    float4 bx4 = *(const float4*)(bxv + n);
    float4 bh4 = *(const float4*)(bhv + n);
#pragma unroll
    for (int i = 0; i < 4; i++) {
        int m = m0 + (ty << 2) + i;
        float2 c0 = unp2(acc[i][0]);
        float2 c1 = unp2(acc[i][1]);
        float4 o;
        o.x = c0.x + bx4.x + bh4.x;
        o.y = c0.y + bx4.y + bh4.y;
        o.z = c1.x + bx4.z + bh4.z;
        o.w = c1.y + bx4.w + bh4.w;
        *(float4*)(g_z0 + (size_t)m * HH + n) = o;
    }
}

// ---------------------------------------------------------------------------
// Persistent sequential kernel. 128 CTAs (1/SM), 256 threads.
// 16 col-groups x 4 batch-groups per layer; CTA tile 32 cols x 16 rows.
// Cross-step prefetch: each CTA stages its NEXT h source during the
// epilogue/handoff, so loop-entry CP_WAIT(0) finds data already arrived.
// L1: A (h1[t-1]) staged BEFORE segB so its arrival hides under segB compute.
// ---------------------------------------------------------------------------
__global__ __launch_bounds__(NTHR) void rnn_seq(
    const float* __restrict__ h_init,
    const float* __restrict__ Wh0,
    const float* __restrict__ Wx1,
    const float* __restrict__ bx1,
    const float* __restrict__ Wh1,
    const float* __restrict__ bh1,
    float* __restrict__ out)
{
    extern __shared__ float sm[];
    const int tid  = threadIdx.x;
    const int bp   = tid & 7;
    const int cg   = (tid >> 3) & 3;
    const int ks   = tid >> 5;          // 0..7
    const int pos  = tid & 31;
    const int bl   = tid & 15;          // reducer: local row
    const int cq   = (tid >> 4) & 7;    // reducer: col quad (tid<128)

    const bool isL0 = blockIdx.x < 64;
    const int  bx   = isL0 ? blockIdx.x : (blockIdx.x - 64);
    const int  colg = bx & 15;
    const int  bg   = bx >> 4;
    const int  n0   = colg * COLS;
    const int  b0   = bg * ROWS;

    if (isL0) {
        // ------------------------- layer 0 -------------------------
        float* wsT  = sm;                        // 4 x GS0
        float* hs   = sm + 4 * GS0;              // [16][HR0]
        float* redf = hs + 16 * HR0;             // [8][RSL]
        const uint32_t sh = (uint32_t)__cvta_generic_to_shared(hs);

        for (int i = tid; i < 4096; i += NTHR) {
            int k = i >> 3, c4 = i & 7;
            float4 v = *(const float4*)(Wh0 + (size_t)k * HH + n0 + c4 * 4);
#pragma unroll
            for (int j = 0; j < 4; j++) {
                int col = c4 * 4 + j;
                float val = (j == 0) ? v.x : (j == 1) ? v.y : (j == 2) ? v.z : v.w;
                wsT[(col >> 3) * GS0 + (col & 7) * WS0 + k] = val;
            }
        }
        __syncthreads();

        const float* hr0 = hs + bp * HR0;
        const float* hr1 = hs + (bp + 8) * HR0;
        const float* wk0 = wsT + cg * GS0;
        const int kio = ks * 32;

        // prologue: stage h for t=0 from h_init
        stage16k<HR0>(sh, h_init + (size_t)b0 * HH, 0, tid);
        stage16k<HR0>(sh, h_init + (size_t)b0 * HH + 256, 256, tid);

        for (int t = 0; t < SEQ; t++) {
            float4 zv;
            if (tid < 128)
                zv = *(const float4*)(g_z0 + (size_t)t * BH
                                      + (size_t)(b0 + bl) * HH + n0 + cq * 4);

            CP_WAIT(0); __syncthreads();     // prefetched h in place

            u64 acc[16];
#pragma unroll
            for (int i = 0; i < 16; i++) acc[i] = 0ULL;

            segN<WS0, 32>(acc, hr0 + kio, hr1 + kio, wk0 + kio);
            segN<WS0, 32>(acc, hr0 + 256 + kio, hr1 + 256 + kio, wk0 + 256 + kio);

            store_partials(redf, acc, ks, pos);
            __syncthreads();
            if (tid < 128) {
                float4 r = reduce8(redf, bl, cq);
                float4 v;
                v.x = tanhf(r.x + zv.x); v.y = tanhf(r.y + zv.y);
                v.z = tanhf(r.z + zv.z); v.w = tanhf(r.w + zv.w);
                *(float4*)(g_h0 + (size_t)t * BH + (size_t)(b0 + bl) * HH
                           + n0 + cq * 4) = v;
                if (t == SEQ - 1)
                    *(float4*)(out + (size_t)SEQ * BH + (size_t)(b0 + bl) * HH
                               + n0 + cq * 4) = v;
            }
            __syncthreads();
            if (tid == 0) {
                red_release(&g_flag0[t * 4 + bg]);
                if (t < SEQ - 1) wait_flag(&g_flag0[t * 4 + bg], 16);
            }
            __syncthreads();
            if (t < SEQ - 1) {   // prefetch h0[t] for step t+1
                const float* hp = g_h0 + (size_t)t * BH + (size_t)b0 * HH;
                stage16k<HR0>(sh, hp, 0, tid);
                stage16k<HR0>(sh, hp + 256, 256, tid);
            }
        }
    } else {
        // ------------------------- layer 1 -------------------------
        // hT cols 0..511 = B (h0[t] @ Wx1), cols 512..1023 = A (h1[t-1] @ Wh1)
        float* wsT  = sm;                        // 4 x GS1
        float* hT   = sm + 4 * GS1;              // [16][HR1]
        float* redf = hT + 16 * HR1;             // [8][RSL]
        const uint32_t sh = (uint32_t)__cvta_generic_to_shared(hT);

        for (int i = tid; i < 8192; i += NTHR) {
            int k = i >> 3, c4 = i & 7;
            float4 v;
            if (k < 512) v = *(const float4*)(Wx1 + (size_t)k * HH + n0 + c4 * 4);
            else         v = *(const float4*)(Wh1 + (size_t)(k - 512) * HH + n0 + c4 * 4);
#pragma unroll
            for (int j = 0; j < 4; j++) {
                int col = c4 * 4 + j;
                float val = (j == 0) ? v.x : (j == 1) ? v.y : (j == 2) ? v.z : v.w;
                wsT[(col >> 3) * GS1 + (col & 7) * WS1 + k] = val;
            }
        }
        float4 bias;
        if (tid < 128) {
            const float* bx4 = bx1 + n0 + cq * 4;
            const float* bh4 = bh1 + n0 + cq * 4;
            bias.x = bx4[0] + bh4[0]; bias.y = bx4[1] + bh4[1];
            bias.z = bx4[2] + bh4[2]; bias.w = bx4[3] + bh4[3];
        }
        __syncthreads();

        const float* hr0 = hT + bp * HR1;
        const float* hr1 = hT + (bp + 8) * HR1;
        const float* wk0 = wsT + cg * GS1;
        const int kio = ks * 32;

        // prologue: wait h0[0], stage B(0)
        if (tid == 0) wait_flag(&g_flag0[0 * 4 + bg], 16);
        __syncthreads();
        {
            const float* h0p = g_h0 + (size_t)b0 * HH;
            stage16k<HR1>(sh, h0p, 0, tid);
            stage16k<HR1>(sh, h0p + 256, 256, tid);
        }

        for (int t = 0; t < SEQ; t++) {
            CP_WAIT(0); __syncthreads();     // B(t) in place

            // confirm h1[t-1] complete across this bg, then stage A early:
            // its ~700cyc arrival hides under segB's ~1400cyc of compute.
            if (t > 0 && tid == 0) wait_flag(&g_flag1[(t - 1) * 4 + bg], 16);
            __syncthreads();
            const float* h1p = ((t == 0) ? (h_init + BH)
                                         : (out + (size_t)(t - 1) * BH))
                               + (size_t)b0 * HH;
            stage16k<HR1>(sh, h1p, 512, tid);
            stage16k<HR1>(sh, h1p + 256, 768, tid);

            u64 acc[16];
#pragma unroll
            for (int i = 0; i < 16; i++) acc[i] = 0ULL;

            segN<WS1, 32>(acc, hr0 + kio, hr1 + kio, wk0 + kio);
            segN<WS1, 32>(acc, hr0 + 256 + kio, hr1 + 256 + kio, wk0 + 256 + kio);

            CP_WAIT(0); __syncthreads();     // A arrived (hidden)
            segN<WS1, 32>(acc, hr0 + 512 + kio, hr1 + 512 + kio, wk0 + 512 + kio);
            segN<WS1, 32>(acc, hr0 + 768 + kio, hr1 + 768 + kio, wk0 + 768 + kio);

            store_partials(redf, acc, ks, pos);
            __syncthreads();
            if (tid < 128) {
                float4 r = reduce8(redf, bl, cq);
                float4 v;
                v.x = tanhf(r.x + bias.x); v.y = tanhf(r.y + bias.y);
                v.z = tanhf(r.z + bias.z); v.w = tanhf(r.w + bias.w);
                *(float4*)(out + (size_t)t * BH + (size_t)(b0 + bl) * HH
                           + n0 + cq * 4) = v;
                if (t == SEQ - 1)
                    *(float4*)(out + (size_t)SEQ * BH + BH
                               + (size_t)(b0 + bl) * HH + n0 + cq * 4) = v;
            }
            __syncthreads();
            if (tid == 0) {
                red_release(&g_flag1[t * 4 + bg]);
                if (t < SEQ - 1) wait_flag(&g_flag0[(t + 1) * 4 + bg], 16);
            }
            __syncthreads();
            if (t < SEQ - 1) {   // prefetch B(t+1) = h0[t+1]
                const float* h0p = g_h0 + (size_t)(t + 1) * BH + (size_t)b0 * HH;
                stage16k<HR1>(sh, h0p, 0, tid);
                stage16k<HR1>(sh, h0p + 256, 256, tid);
            }
        }
    }
}

// L1: (4*8200 + 16*1044 + 8*640)*4 = (32800+16704+5120)*4 = 218496 B
// L0: (4*4104 + 16*516 + 8*640)*4  = (16416+8256+5120)*4  = 119168 B
#define SMEM_BYTES 218496

extern "C" void kernel_launch(void* const* d_in, const int* in_sizes, int n_in,
                              void* d_out, int out_size)
{
    const float* x   = (const float*)d_in[0];
    const float* h0  = (const float*)d_in[1];
    const float* Wx0 = (const float*)d_in[2];
    const float* bx0 = (const float*)d_in[3];
    const float* Wh0 = (const float*)d_in[4];
    const float* bh0 = (const float*)d_in[5];
    const float* Wx1 = (const float*)d_in[6];
    const float* bx1 = (const float*)d_in[7];
    const float* Wh1 = (const float*)d_in[8];
    const float* bh1 = (const float*)d_in[9];
    float* out = (float*)d_out;
    (void)in_sizes; (void)n_in; (void)out_size;

    dim3 gz((SEQ * BB) / 64, HH / 64);
    precompute_z0<<<gz, 256>>>(x, Wx0, bx0, bh0);

    static int attr_set = 0;
    if (!attr_set) {
        cudaFuncSetAttribute(rnn_seq, cudaFuncAttributeMaxDynamicSharedMemorySize,
                             SMEM_BYTES);
        attr_set = 1;
    }
    rnn_seq<<<128, NTHR, SMEM_BYTES>>>(h0, Wh0, Wx1, bx1, Wh1, bh1, out);
}

// round 15
// speedup vs baseline: 1.2752x; 1.2752x over previous
#include <cuda_runtime.h>
#include <math.h>
#include <stdint.h>

#define SEQ 1024
#define BB  64
#define DD  512
#define HH  512
#define BH  (BB * HH)

#define NTHR 256
#define ROWS 16      // batch rows per CTA
#define COLS 32      // cols per CTA

typedef unsigned long long u64;

// Scratch (allocation-free rule: __device__ globals)
__device__ float g_h0[SEQ * BB * HH];   // layer-0 hidden history (b-major)
__device__ int   g_flag0[SEQ * 4];      // per (t, batch-group), target 16
__device__ int   g_flag1[SEQ * 4];

// ---------------------------------------------------------------- helpers
__device__ __forceinline__ int ld_acq(const int* p) {
    int v;
    asm volatile("ld.acquire.gpu.s32 %0, [%1];" : "=r"(v) : "l"(p) : "memory");
    return v;
}
__device__ __forceinline__ void red_release(int* p) {
    asm volatile("red.release.gpu.global.add.s32 [%0], 1;" :: "l"(p) : "memory");
}
__device__ __forceinline__ void wait_flag(const int* p, int target) {
    while (ld_acq(p) < target) {}
}
__device__ __forceinline__ void fma2(u64& acc, u64 a, u64 b) {
    asm("fma.rn.f32x2 %0, %1, %2, %0;" : "+l"(acc) : "l"(a), "l"(b));
}
__device__ __forceinline__ float2 unp2(u64 v) {
    float2 f; asm("mov.b64 {%0, %1}, %2;" : "=f"(f.x), "=f"(f.y) : "l"(v)); return f;
}
__device__ __forceinline__ float fold2(u64 v) {
    float2 f = unp2(v); return f.x + f.y;
}
__device__ __forceinline__ void cp16(uint32_t s, const void* g) {
    asm volatile("cp.async.cg.shared.global [%0], [%1], 16;" :: "r"(s), "l"(g));
}
__device__ __forceinline__ void cp_commit() {
    asm volatile("cp.async.commit_group;" ::: "memory");
}
#define CP_WAIT(N) asm volatile("cp.async.wait_group %0;" :: "n"(N) : "memory")

// w layout: 4 cg-groups of [8 rows][WS floats], group stride GS = 8*WS + 8.
// cg lane offsets mod 32 floats = {0,8,16,24} -> distinct quad banks.
#define WS 1024
#define GS (8 * WS + 8)      // 8200
#define HR 1044              // h row stride: bp offsets mod 32 all distinct
#define RBG 20               // red floats per pos (16 + 4 pad)
#define RSL (32 * RBG)       // 640 floats per k-slice

// Stage 16 rows x 256 k (16KB) into h buffer at column kdst. 4 cp16/thread.
__device__ __forceinline__ void stage16k(uint32_t sbase, const float* src,
                                         int kdst, int tid) {
#pragma unroll
    for (int j = 0; j < 4; j++) {
        int id = tid + j * NTHR;            // 0..1023
        int b = id >> 6, ku = id & 63;
        cp16(sbase + (uint32_t)((b * HR + kdst + ku * 4) * 4),
             src + (size_t)b * HH + ku * 4);
    }
    cp_commit();
}

// 32-k segment: 2 rows x 8 cols per thread, K-packed f32x2.
__device__ __forceinline__ void seg32(u64* acc, const float* hr0, const float* hr1,
                                      const float* wk)
{
#pragma unroll
    for (int i = 0; i < 32; i += 4) {
        ulonglong2 ha = *(const ulonglong2*)(hr0 + i);
        ulonglong2 hb = *(const ulonglong2*)(hr1 + i);
#pragma unroll
        for (int c = 0; c < 8; c++) {
            ulonglong2 w = *(const ulonglong2*)(wk + c * WS + i);
            fma2(acc[c],     ha.x, w.x);  fma2(acc[c],     ha.y, w.y);
            fma2(acc[8 + c], hb.x, w.x);  fma2(acc[8 + c], hb.y, w.y);
        }
    }
}

// Fold 16 u64 partials to floats, store to red[ks][pos][16] (20-padded).
__device__ __forceinline__ void store_partials(float* redf, const u64* acc,
                                               int ks, int pos) {
    float tmp[16];
#pragma unroll
    for (int j = 0; j < 16; j++) tmp[j] = fold2(acc[j]);
    float* wr = redf + (size_t)ks * RSL + (size_t)pos * RBG;
#pragma unroll
    for (int j = 0; j < 4; j++)
        *(float4*)(wr + 4 * j) = make_float4(tmp[4*j], tmp[4*j+1], tmp[4*j+2], tmp[4*j+3]);
}

// Reduce 8 k-slices for output (local row bl 0..15, col quad cq 0..7).
__device__ __forceinline__ float4 reduce8(const float* redf, int bl, int cq) {
    const float* rp = redf + (size_t)((cq >> 1) * 8 + (bl & 7)) * RBG
                    + (bl >> 3) * 8 + (cq & 1) * 4;
    float4 s = make_float4(0.f, 0.f, 0.f, 0.f);
#pragma unroll
    for (int ks = 0; ks < 8; ks++) {
        float4 p = *(const float4*)(rp + (size_t)ks * RSL);
        s.x += p.x; s.y += p.y; s.z += p.z; s.w += p.w;
    }
    return s;
}

__global__ void init_flags() {
    int i = blockIdx.x * 256 + threadIdx.x;
    if (i < SEQ * 4) { g_flag0[i] = 0; g_flag1[i] = 0; }
}

// ---------------------------------------------------------------------------
// Persistent kernel. 128 CTAs (1/SM), 256 threads. Both layers are the SAME
// K=1024 concat GEMV:
//   L0: h0[t] = tanh([x[t]   ; h0[t-1]] @ [Wx0; Wh0] + b0)   blocks [0,64)
//   L1: h1[t] = tanh([h0[t]  ; h1[t-1]] @ [Wx1; Wh1] + b1)   blocks [64,128)
// 16 col-groups x 4 batch-groups each; CTA tile 32 cols x 16 rows.
// hT: cols 0..511 = B part, 512..1023 = A part. Flags per (t,bg), 16 producers.
// Per-step barriers: 2 data bars + reduce bar + pre-release bar = 4.
// B(t+1) prefetched at step end (x: no flag; L1: flag0[t+1], all-thread poll).
// A staged at step top after all-thread poll of the recurrence flag.
// ---------------------------------------------------------------------------
__global__ __launch_bounds__(NTHR) void rnn_seq(
    const float* __restrict__ x,
    const float* __restrict__ h_init,
    const float* __restrict__ Wx0,
    const float* __restrict__ bx0,
    const float* __restrict__ Wh0,
    const float* __restrict__ bh0,
    const float* __restrict__ Wx1,
    const float* __restrict__ bx1,
    const float* __restrict__ Wh1,
    const float* __restrict__ bh1,
    float* __restrict__ out)
{
    extern __shared__ float sm[];
    const int tid  = threadIdx.x;
    const int bp   = tid & 7;
    const int cg   = (tid >> 3) & 3;
    const int ks   = tid >> 5;          // 0..7
    const int pos  = tid & 31;
    const int bl   = tid & 15;          // reducer: local row
    const int cq   = (tid >> 4) & 7;    // reducer: col quad (tid<128)

    const bool isL0 = blockIdx.x < 64;
    const int  bx   = isL0 ? blockIdx.x : (blockIdx.x - 64);
    const int  colg = bx & 15;
    const int  bg   = bx >> 4;
    const int  n0   = colg * COLS;
    const int  b0   = bg * ROWS;

    const float* wB = isL0 ? Wx0 : Wx1;      // K part 0..511
    const float* wA = isL0 ? Wh0 : Wh1;      // K part 512..1023
    int* flagSelf   = isL0 ? g_flag0 : g_flag1;
    int* flagAwait  = flagSelf;              // A = own layer's recurrence

    float* wsT  = sm;                        // 4 x GS
    float* hT   = sm + 4 * GS;               // [16][HR]
    float* redf = hT + 16 * HR;              // [8][RSL]
    const uint32_t sh = (uint32_t)__cvta_generic_to_shared(hT);

    // weights: concat K, cg-skewed bank-clean layout
    for (int i = tid; i < 8192; i += NTHR) {
        int k = i >> 3, c4 = i & 7;
        float4 v;
        if (k < 512) v = *(const float4*)(wB + (size_t)k * HH + n0 + c4 * 4);
        else         v = *(const float4*)(wA + (size_t)(k - 512) * HH + n0 + c4 * 4);
#pragma unroll
        for (int j = 0; j < 4; j++) {
            int col = c4 * 4 + j;
            float val = (j == 0) ? v.x : (j == 1) ? v.y : (j == 2) ? v.z : v.w;
            wsT[(col >> 3) * GS + (col & 7) * WS + k] = val;
        }
    }
    float4 bias;
    if (tid < 128) {
        const float* bxp = (isL0 ? bx0 : bx1) + n0 + cq * 4;
        const float* bhp = (isL0 ? bh0 : bh1) + n0 + cq * 4;
        bias.x = bxp[0] + bhp[0]; bias.y = bxp[1] + bhp[1];
        bias.z = bxp[2] + bhp[2]; bias.w = bxp[3] + bhp[3];
    }
    __syncthreads();

    const float* hr0 = hT + bp * HR;
    const float* hr1 = hT + (bp + 8) * HR;
    const float* wk0 = wsT + cg * GS;
    const int kio = ks * 32;

    // prologue: stage B(0)
    {
        const float* bsrc;
        if (isL0) {
            bsrc = x + (size_t)b0 * HH;                 // x[0], no flag
        } else {
            wait_flag(&g_flag0[0 * 4 + bg], 16);        // all-thread poll
            bsrc = g_h0 + (size_t)b0 * HH;
        }
        stage16k(sh, bsrc, 0, tid);
        stage16k(sh, bsrc + 256, 256, tid);
    }

    for (int t = 0; t < SEQ; t++) {
        // ---- stage A = own h[t-1] (all-thread poll, no bar) ----
        if (t > 0) wait_flag(&flagAwait[(t - 1) * 4 + bg], 16);
        const float* asrc;
        if (t == 0) asrc = (isL0 ? h_init : (h_init + BH)) + (size_t)b0 * HH;
        else        asrc = (isL0 ? (g_h0 + (size_t)(t - 1) * BH)
                                 : (out + (size_t)(t - 1) * BH)) + (size_t)b0 * HH;
        stage16k(sh, asrc, 512, tid);
        stage16k(sh, asrc + 256, 768, tid);

        u64 acc[16];
#pragma unroll
        for (int i = 0; i < 16; i++) acc[i] = 0ULL;

        CP_WAIT(2); __syncthreads();          // B(t) ready (A outstanding)
        seg32(acc, hr0 + kio, hr1 + kio, wk0 + kio);
        seg32(acc, hr0 + 256 + kio, hr1 + 256 + kio, wk0 + 256 + kio);

        CP_WAIT(0); __syncthreads();          // A ready (arrival hidden)
        seg32(acc, hr0 + 512 + kio, hr1 + 512 + kio, wk0 + 512 + kio);
        seg32(acc, hr0 + 768 + kio, hr1 + 768 + kio, wk0 + 768 + kio);

        store_partials(redf, acc, ks, pos);
        __syncthreads();
        if (tid < 128) {
            float4 r = reduce8(redf, bl, cq);
            float4 v;
            v.x = tanhf(r.x + bias.x); v.y = tanhf(r.y + bias.y);
            v.z = tanhf(r.z + bias.z); v.w = tanhf(r.w + bias.w);
            float* dst = (isL0 ? g_h0 : out) + (size_t)t * BH
                         + (size_t)(b0 + bl) * HH + n0 + cq * 4;
            *(float4*)dst = v;
            if (t == SEQ - 1) {
                float* hn = out + (size_t)SEQ * BH + (isL0 ? 0 : BH)
                            + (size_t)(b0 + bl) * HH + n0 + cq * 4;
                *(float4*)hn = v;
            }
        }
        __syncthreads();
        if (tid == 0) red_release(&flagSelf[t * 4 + bg]);

        // ---- prefetch B(t+1) (all-thread poll where needed, no bar) ----
        if (t < SEQ - 1) {
            const float* bsrc;
            if (isL0) {
                bsrc = x + (size_t)(t + 1) * BH + (size_t)b0 * HH;   // no flag
            } else {
                wait_flag(&g_flag0[(t + 1) * 4 + bg], 16);
                bsrc = g_h0 + (size_t)(t + 1) * BH + (size_t)b0 * HH;
            }
            stage16k(sh, bsrc, 0, tid);
            stage16k(sh, bsrc + 256, 256, tid);
        }
    }
}

// smem: (4*8200 + 16*1044 + 8*640)*4 = (32800+16704+5120)*4 = 218496 B
#define SMEM_BYTES 218496

extern "C" void kernel_launch(void* const* d_in, const int* in_sizes, int n_in,
                              void* d_out, int out_size)
{
    const float* x   = (const float*)d_in[0];
    const float* h0  = (const float*)d_in[1];
    const float* Wx0 = (const float*)d_in[2];
    const float* bx0 = (const float*)d_in[3];
    const float* Wh0 = (const float*)d_in[4];
    const float* bh0 = (const float*)d_in[5];
    const float* Wx1 = (const float*)d_in[6];
    const float* bx1 = (const float*)d_in[7];
    const float* Wh1 = (const float*)d_in[8];
    const float* bh1 = (const float*)d_in[9];
    float* out = (float*)d_out;
    (void)in_sizes; (void)n_in; (void)out_size;

    init_flags<<<32, 256>>>();

    static int attr_set = 0;
    if (!attr_set) {
        cudaFuncSetAttribute(rnn_seq, cudaFuncAttributeMaxDynamicSharedMemorySize,
                             SMEM_BYTES);
        attr_set = 1;
    }
    rnn_seq<<<128, NTHR, SMEM_BYTES>>>(x, h0, Wx0, bx0, Wh0, bh0,
                                       Wx1, bx1, Wh1, bh1, out);
}

// round 17
// speedup vs baseline: 1.2811x; 1.0046x over previous
#include <cuda_runtime.h>
#include <math.h>
#include <stdint.h>

#define SEQ 1024
#define BB  64
#define DD  512
#define HH  512
#define BH  (BB * HH)

#define NTHR 256
#define ROWS 16      // batch rows per CTA
#define COLS 32      // cols per CTA

typedef unsigned long long u64;

// Scratch (allocation-free rule: __device__ globals)
__device__ float g_h0[SEQ * BB * HH];   // layer-0 hidden history (b-major)
__device__ int   g_flag0[SEQ * 4];      // per (t, batch-group), target 16
__device__ int   g_flag1[SEQ * 4];

// ---------------------------------------------------------------- helpers
__device__ __forceinline__ int ld_acq(const int* p) {
    int v;
    asm volatile("ld.acquire.gpu.s32 %0, [%1];" : "=r"(v) : "l"(p) : "memory");
    return v;
}
__device__ __forceinline__ void red_release(int* p) {
    asm volatile("red.release.gpu.global.add.s32 [%0], 1;" :: "l"(p) : "memory");
}
__device__ __forceinline__ void wait_flag(const int* p, int target) {
    while (ld_acq(p) < target) {}
}
__device__ __forceinline__ void fma2(u64& acc, u64 a, u64 b) {
    asm("fma.rn.f32x2 %0, %1, %2, %0;" : "+l"(acc) : "l"(a), "l"(b));
}
__device__ __forceinline__ float2 unp2(u64 v) {
    float2 f; asm("mov.b64 {%0, %1}, %2;" : "=f"(f.x), "=f"(f.y) : "l"(v)); return f;
}
__device__ __forceinline__ float fold2(u64 v) {
    float2 f = unp2(v); return f.x + f.y;
}
__device__ __forceinline__ void cp16(uint32_t s, const void* g) {
    asm volatile("cp.async.cg.shared.global [%0], [%1], 16;" :: "r"(s), "l"(g));
}
__device__ __forceinline__ void cp_commit() {
    asm volatile("cp.async.commit_group;" ::: "memory");
}
#define CP_WAIT(N) asm volatile("cp.async.wait_group %0;" :: "n"(N) : "memory")

// w layout: 8 cg-groups of [4 cols][WS floats], group stride GS = 4*WS + 4.
// cg quad offsets = cg*1025 mod 32 = {0..7}*1 -> 8 distinct quads, full phases.
#define WS 1024
#define GS (4 * WS + 4)      // 4100
#define HR 1044              // h row stride: bp*261 mod 32 -> {0,5,10,15} etc.
#define RBG 20               // red floats per pos (16 + 4 pad)
#define RSL (32 * RBG)       // 640 floats per k-slice

// Stage 16 rows x 256 k (16KB) into h buffer at column kdst. 4 cp16/thread.
__device__ __forceinline__ void stage16k(uint32_t sbase, const float* src,
                                         int kdst, int tid) {
#pragma unroll
    for (int j = 0; j < 4; j++) {
        int id = tid + j * NTHR;            // 0..1023
        int b = id >> 6, ku = id & 63;
        cp16(sbase + (uint32_t)((b * HR + kdst + ku * 4) * 4),
             src + (size_t)b * HH + ku * 4);
    }
    cp_commit();
}

// 32-k segment: 4 rows x 4 cols per thread, K-packed f32x2.
// h: 4 distinct bp rows x broadcast-8 (1 phase); w: 8 distinct cg quads (full).
// acc[m*4+c], m = row group (bp+4m), c = col within cg.
__device__ __forceinline__ void seg32(u64* acc,
                                      const float* h0, const float* h1,
                                      const float* h2, const float* h3,
                                      const float* wk)
{
#pragma unroll
    for (int i = 0; i < 32; i += 4) {
        ulonglong2 ha = *(const ulonglong2*)(h0 + i);
        ulonglong2 hb = *(const ulonglong2*)(h1 + i);
        ulonglong2 hc = *(const ulonglong2*)(h2 + i);
        ulonglong2 hd = *(const ulonglong2*)(h3 + i);
#pragma unroll
        for (int c = 0; c < 4; c++) {
            ulonglong2 w = *(const ulonglong2*)(wk + c * WS + i);
            fma2(acc[c],      ha.x, w.x);  fma2(acc[c],      ha.y, w.y);
            fma2(acc[4 + c],  hb.x, w.x);  fma2(acc[4 + c],  hb.y, w.y);
            fma2(acc[8 + c],  hc.x, w.x);  fma2(acc[8 + c],  hc.y, w.y);
            fma2(acc[12 + c], hd.x, w.x);  fma2(acc[12 + c], hd.y, w.y);
        }
    }
}

// Fold 16 u64 partials to floats, store to red[ks][pos][16] (20-padded).
// pos = cg*4 + bp; quad = 5*pos mod 32 bijective -> conflict-free.
__device__ __forceinline__ void store_partials(float* redf, const u64* acc,
                                               int ks, int pos) {
    float tmp[16];
#pragma unroll
    for (int j = 0; j < 16; j++) tmp[j] = fold2(acc[j]);
    float* wr = redf + (size_t)ks * RSL + (size_t)pos * RBG;
#pragma unroll
    for (int j = 0; j < 4; j++)
        *(float4*)(wr + 4 * j) = make_float4(tmp[4*j], tmp[4*j+1], tmp[4*j+2], tmp[4*j+3]);
}

// Reduce 8 k-slices for output (local row bl 0..15, col quad cq 0..7).
// Partial for (row bl, colquad cq) lives at pos = cq*4 + (bl&3),
// tmp index = (bl>>2)*4 + c.
__device__ __forceinline__ float4 reduce8(const float* redf, int bl, int cq) {
    const float* rp = redf + (size_t)(cq * 4 + (bl & 3)) * RBG + (bl >> 2) * 4;
    float4 s = make_float4(0.f, 0.f, 0.f, 0.f);
#pragma unroll
    for (int ks = 0; ks < 8; ks++) {
        float4 p = *(const float4*)(rp + (size_t)ks * RSL);
        s.x += p.x; s.y += p.y; s.z += p.z; s.w += p.w;
    }
    return s;
}

__global__ void init_flags() {
    int i = blockIdx.x * 256 + threadIdx.x;
    if (i < SEQ * 4) { g_flag0[i] = 0; g_flag1[i] = 0; }
}

// ---------------------------------------------------------------------------
// Persistent kernel. 128 CTAs (1/SM), 256 threads. Both layers are the SAME
// K=1024 concat GEMV:
//   L0: h0[t] = tanh([x[t]  ; h0[t-1]] @ [Wx0; Wh0] + b0)   blocks [0,64)
//   L1: h1[t] = tanh([h0[t] ; h1[t-1]] @ [Wx1; Wh1] + b1)   blocks [64,128)
// 16 col-groups x 4 batch-groups each; CTA tile 32 cols x 16 rows.
// Thread: bp=tid&3 (rows bp+4m), cg=(tid>>2)&7 (4 cols), ks=tid>>5.
// K schedule per thread: kio + {0, 256, 512, 768}, kio = ks*32
//   (8 ks-slices x 128 k each = 1024 k total; B = first two, A = last two).
// ---------------------------------------------------------------------------
__global__ __launch_bounds__(NTHR) void rnn_seq(
    const float* __restrict__ x,
    const float* __restrict__ h_init,
    const float* __restrict__ Wx0,
    const float* __restrict__ bx0,
    const float* __restrict__ Wh0,
    const float* __restrict__ bh0,
    const float* __restrict__ Wx1,
    const float* __restrict__ bx1,
    const float* __restrict__ Wh1,
    const float* __restrict__ bh1,
    float* __restrict__ out)
{
    extern __shared__ float sm[];
    const int tid  = threadIdx.x;
    const int bp   = tid & 3;
    const int cg   = (tid >> 2) & 7;
    const int ks   = tid >> 5;          // 0..7
    const int pos  = tid & 31;          // cg*4 + bp
    const int bl   = tid & 15;          // reducer: local row
    const int cq   = (tid >> 4) & 7;    // reducer: col quad (tid<128)

    const bool isL0 = blockIdx.x < 64;
    const int  bx   = isL0 ? blockIdx.x : (blockIdx.x - 64);
    const int  colg = bx & 15;
    const int  bg   = bx >> 4;
    const int  n0   = colg * COLS;
    const int  b0   = bg * ROWS;

    const float* wB = isL0 ? Wx0 : Wx1;      // K part 0..511
    const float* wA = isL0 ? Wh0 : Wh1;      // K part 512..1023
    int* flagSelf   = isL0 ? g_flag0 : g_flag1;

    float* wsT  = sm;                        // 8 x GS = 32800 floats
    float* hT   = sm + 8 * GS;               // [16][HR]
    float* redf = hT + 16 * HR;              // [8][RSL]
    const uint32_t sh = (uint32_t)__cvta_generic_to_shared(hT);

    // weights: concat K, 8-group bank-clean layout (col>>2 group, col&3 inner)
    for (int i = tid; i < 8192; i += NTHR) {
        int k = i >> 3, c4 = i & 7;
        float4 v;
        if (k < 512) v = *(const float4*)(wB + (size_t)k * HH + n0 + c4 * 4);
        else         v = *(const float4*)(wA + (size_t)(k - 512) * HH + n0 + c4 * 4);
#pragma unroll
        for (int j = 0; j < 4; j++) {
            int col = c4 * 4 + j;
            float val = (j == 0) ? v.x : (j == 1) ? v.y : (j == 2) ? v.z : v.w;
            wsT[(col >> 2) * GS + (col & 3) * WS + k] = val;
        }
    }
    float4 bias;
    if (tid < 128) {
        const float* bxp = (isL0 ? bx0 : bx1) + n0 + cq * 4;
        const float* bhp = (isL0 ? bh0 : bh1) + n0 + cq * 4;
        bias.x = bxp[0] + bhp[0]; bias.y = bxp[1] + bhp[1];
        bias.z = bxp[2] + bhp[2]; bias.w = bxp[3] + bhp[3];
    }
    __syncthreads();

    const float* hr0 = hT + (bp +  0) * HR;
    const float* hr1 = hT + (bp +  4) * HR;
    const float* hr2 = hT + (bp +  8) * HR;
    const float* hr3 = hT + (bp + 12) * HR;
    const float* wk0 = wsT + cg * GS;
    const int kio = ks * 32;

    // prologue: stage B(0)
    {
        const float* bsrc;
        if (isL0) {
            bsrc = x + (size_t)b0 * HH;                 // x[0], no flag
        } else {
            wait_flag(&g_flag0[0 * 4 + bg], 16);        // all-thread poll
            bsrc = g_h0 + (size_t)b0 * HH;
        }
        stage16k(sh, bsrc, 0, tid);
        stage16k(sh, bsrc + 256, 256, tid);
    }

    for (int t = 0; t < SEQ; t++) {
        // ---- stage A = own h[t-1] (all-thread poll, no bar) ----
        if (t > 0) wait_flag(&flagSelf[(t - 1) * 4 + bg], 16);
        const float* asrc;
        if (t == 0) asrc = (isL0 ? h_init : (h_init + BH)) + (size_t)b0 * HH;
        else        asrc = (isL0 ? (g_h0 + (size_t)(t - 1) * BH)
                                 : (out + (size_t)(t - 1) * BH)) + (size_t)b0 * HH;
        stage16k(sh, asrc, 512, tid);
        stage16k(sh, asrc + 256, 768, tid);

        u64 acc[16];
#pragma unroll
        for (int i = 0; i < 16; i++) acc[i] = 0ULL;

        CP_WAIT(2); __syncthreads();          // B(t) ready (A outstanding)
        seg32(acc, hr0 + kio, hr1 + kio, hr2 + kio, hr3 + kio, wk0 + kio);
        seg32(acc, hr0 + 256 + kio, hr1 + 256 + kio, hr2 + 256 + kio,
              hr3 + 256 + kio, wk0 + 256 + kio);

        CP_WAIT(0); __syncthreads();          // A ready (arrival hidden)
        seg32(acc, hr0 + 512 + kio, hr1 + 512 + kio, hr2 + 512 + kio,
              hr3 + 512 + kio, wk0 + 512 + kio);
        seg32(acc, hr0 + 768 + kio, hr1 + 768 + kio, hr2 + 768 + kio,
              hr3 + 768 + kio, wk0 + 768 + kio);

        store_partials(redf, acc, ks, pos);
        __syncthreads();
        if (tid < 128) {
            float4 r = reduce8(redf, bl, cq);
            float4 v;
            v.x = tanhf(r.x + bias.x); v.y = tanhf(r.y + bias.y);
            v.z = tanhf(r.z + bias.z); v.w = tanhf(r.w + bias.w);
            float* dst = (isL0 ? g_h0 : out) + (size_t)t * BH
                         + (size_t)(b0 + bl) * HH + n0 + cq * 4;
            *(float4*)dst = v;
            if (t == SEQ - 1) {
                float* hn = out + (size_t)SEQ * BH + (isL0 ? 0 : BH)
                            + (size_t)(b0 + bl) * HH + n0 + cq * 4;
                *(float4*)hn = v;
            }
        }
        __syncthreads();
        if (tid == 0) red_release(&flagSelf[t * 4 + bg]);

        // ---- prefetch B(t+1) (all-thread poll where needed, no bar) ----
        if (t < SEQ - 1) {
            const float* bsrc;
            if (isL0) {
                bsrc = x + (size_t)(t + 1) * BH + (size_t)b0 * HH;   // no flag
            } else {
                wait_flag(&g_flag0[(t + 1) * 4 + bg], 16);
                bsrc = g_h0 + (size_t)(t + 1) * BH + (size_t)b0 * HH;
            }
            stage16k(sh, bsrc, 0, tid);
            stage16k(sh, bsrc + 256, 256, tid);
        }
    }
}

// smem: (8*4100 + 16*1044 + 8*640)*4 = (32800+16704+5120)*4 = 218496 B
#define SMEM_BYTES 218496

extern "C" void kernel_launch(void* const* d_in, const int* in_sizes, int n_in,
                              void* d_out, int out_size)
{
    const float* x   = (const float*)d_in[0];
    const float* h0  = (const float*)d_in[1];
    const float* Wx0 = (const float*)d_in[2];
    const float* bx0 = (const float*)d_in[3];
    const float* Wh0 = (const float*)d_in[4];
    const float* bh0 = (const float*)d_in[5];
    const float* Wx1 = (const float*)d_in[6];
    const float* bx1 = (const float*)d_in[7];
    const float* Wh1 = (const float*)d_in[8];
    const float* bh1 = (const float*)d_in[9];
    float* out = (float*)d_out;
    (void)in_sizes; (void)n_in; (void)out_size;

    init_flags<<<32, 256>>>();

    static int attr_set = 0;
    if (!attr_set) {
        cudaFuncSetAttribute(rnn_seq, cudaFuncAttributeMaxDynamicSharedMemorySize,
                             SMEM_BYTES);
        attr_set = 1;
    }
    rnn_seq<<<128, NTHR, SMEM_BYTES>>>(x, h0, Wx0, bx0, Wh0, bh0,
                                       Wx1, bx1, Wh1, bh1, out);
}